// round 7
// baseline (speedup 1.0000x reference)
#include <cuda_runtime.h>
#include <cuda_bf16.h>
#include <cstdint>
#include <math.h>

#define BATCH 8192
#define IN1   49
#define HID   256
#define NCOEF 13
#define KP1   704      // 49*14 = 686, padded to 64-multiple
#define K2    3584     // 256*14
#define OUT3  10

// ================= helpers (baseline PTX only: sm_80-era features) =================
__device__ __forceinline__ uint32_t smem_to_u32(const void* p) {
    uint32_t a;
    asm("{ .reg .u64 t; cvta.to.shared.u64 t, %1; cvt.u32.u64 %0, t; }" : "=r"(a) : "l"(p));
    return a;
}

#define CP16(dst, src) \
    asm volatile("cp.async.cg.shared.global [%0], [%1], 16;" :: "r"(dst), "l"(src) : "memory")
#define CP_COMMIT() asm volatile("cp.async.commit_group;" ::: "memory")
#define CP_WAIT2()  asm volatile("cp.async.wait_group 2;" ::: "memory")
#define CP_WAIT1()  asm volatile("cp.async.wait_group 1;" ::: "memory")
#define CP_WAIT0()  asm volatile("cp.async.wait_group 0;" ::: "memory")

#define LDSM4(r, addr) \
    asm volatile("ldmatrix.sync.aligned.m8n8.x4.shared.b16 {%0,%1,%2,%3}, [%4];" \
        : "=r"((r)[0]), "=r"((r)[1]), "=r"((r)[2]), "=r"((r)[3]) : "r"(addr))

#define MMA_BF16(d, a, b0, b1) \
    asm volatile("mma.sync.aligned.m16n8k16.row.col.f32.bf16.bf16.f32 " \
        "{%0,%1,%2,%3},{%4,%5,%6,%7},{%8,%9},{%0,%1,%2,%3};" \
        : "+f"((d)[0]), "+f"((d)[1]), "+f"((d)[2]), "+f"((d)[3]) \
        : "r"((a)[0]), "r"((a)[1]), "r"((a)[2]), "r"((a)[3]), "r"(b0), "r"(b1))

// ================= scratch =================
__device__ float         g_H [BATCH * HID];
__device__ __nv_bfloat16 g_Ah[(size_t)BATCH * K2];
__device__ __nv_bfloat16 g_Al[(size_t)BATCH * K2];
__device__ __nv_bfloat16 g_Wh1[HID * KP1];
__device__ __nv_bfloat16 g_Wl1[HID * KP1];
__device__ __nv_bfloat16 g_Wh2[HID * K2];
__device__ __nv_bfloat16 g_Wl2[HID * K2];
__device__ float         g_W3[K2 * OUT3];

// ================= shared KAN basis math =================
__device__ __forceinline__ void kan_basis(float xv, float& mishv, float* Bv) {
    float sp = fmaxf(xv, 0.f) + log1pf(expf(-fabsf(xv)));
    mishv = xv * tanhf(sp);
    const float h = 0.4f;
#pragma unroll
    for (int j = 0; j < 16; j++) {
        float t0 = -2.0f + h * (float)(j - 3);
        float t1 = -2.0f + h * (float)(j - 2);
        Bv[j] = (xv >= t0 && xv < t1) ? 1.0f : 0.0f;
    }
#pragma unroll
    for (int d = 1; d <= 3; d++) {
        float inv = 1.0f / (h * (float)d);
#pragma unroll
        for (int j = 0; j < 16 - 3; j++) {
            if (j < 16 - d) {
                float tj   = -2.0f + h * (float)(j - 3);
                float tjd1 = -2.0f + h * (float)(j - 3 + d + 1);
                Bv[j] = (xv - tj) * inv * Bv[j] + (tjd1 - xv) * inv * Bv[j + 1];
            }
        }
        if (d < 3) {
            for (int j = 13; j < 16 - d; j++) {
                float tj   = -2.0f + h * (float)(j - 3);
                float tjd1 = -2.0f + h * (float)(j - 3 + d + 1);
                Bv[j] = (xv - tj) * inv * Bv[j] + (tjd1 - xv) * inv * Bv[j + 1];
            }
        }
    }
}

__device__ __forceinline__ void split_hl(float v, __nv_bfloat16& hi, __nv_bfloat16& lo) {
    hi = __float2bfloat16(v);
    lo = __float2bfloat16(v - __bfloat162float(hi));
}

// ========== expand for in=256 (layers 2/3): 1 batch row per block, smem-staged ==========
__global__ __launch_bounds__(256)
void expand256_kernel(const float* __restrict__ H, __nv_bfloat16* __restrict__ Ah,
                      __nv_bfloat16* __restrict__ Al) {
    __shared__ __nv_bfloat16 sh[K2];
    __shared__ __nv_bfloat16 sl[K2];
    int b = blockIdx.x, i = threadIdx.x;
    float xv = H[b * HID + i];
    float mishv, Bv[16];
    kan_basis(xv, mishv, Bv);
    split_hl(mishv, sh[i], sl[i]);
    int off = HID + i * NCOEF;
#pragma unroll
    for (int g = 0; g < NCOEF; g++) split_hl(Bv[g], sh[off + g], sl[off + g]);
    __syncthreads();

    const uint4* s4h = (const uint4*)sh;
    const uint4* s4l = (const uint4*)sl;
    uint4* oh = (uint4*)(Ah + (size_t)b * K2);
    uint4* ol = (uint4*)(Al + (size_t)b * K2);
#pragma unroll
    for (int u = 0; u < 2; u++) {
        int t = u * 256 + i;
        if (t < 448) { oh[t] = s4h[t]; ol[t] = s4l[t]; }
    }
}

// ========== expand for layer 1: fused pool + basis + pad; 4 batch rows per block ==========
__global__ __launch_bounds__(256)
void expand49_kernel(const float* __restrict__ x, __nv_bfloat16* __restrict__ Ah,
                     __nv_bfloat16* __restrict__ Al) {
    __shared__ __nv_bfloat16 sh[4 * KP1];
    __shared__ __nv_bfloat16 sl[4 * KP1];
    int t = threadIdx.x;
    int b0 = blockIdx.x * 4;
    __nv_bfloat16 z = __float2bfloat16(0.f);

    if (t < 72) {
        int r = t / 18, c = 686 + (t - (t / 18) * 18);
        sh[r * KP1 + c] = z;
        sl[r * KP1 + c] = z;
    }

    if (t < 196) {
        int r = t / 49, i = t - r * 49;
        int b = b0 + r;
        int pr = i / 7, pc = i - pr * 7;
        const float* base = x + (size_t)b * 784 + pr * 4 * 28 + pc * 4;
        float s = 0.f;
#pragma unroll
        for (int k = 0; k < 4; k++) {
            float4 v = *(const float4*)(base + k * 28);
            s += v.x + v.y + v.z + v.w;
        }
        float xv = s * 0.0625f;
        float mishv, Bv[16];
        kan_basis(xv, mishv, Bv);
        __nv_bfloat16* rh = sh + r * KP1;
        __nv_bfloat16* rl = sl + r * KP1;
        split_hl(mishv, rh[i], rl[i]);
        int off = IN1 + i * NCOEF;
#pragma unroll
        for (int g = 0; g < NCOEF; g++) split_hl(Bv[g], rh[off + g], rl[off + g]);
    }
    __syncthreads();

    const uint4* s4h = (const uint4*)sh;
    const uint4* s4l = (const uint4*)sl;
    uint4* oh = (uint4*)(Ah + (size_t)b0 * KP1);
    uint4* ol = (uint4*)(Al + (size_t)b0 * KP1);
#pragma unroll
    for (int u = 0; u < 2; u++) {
        int w = u * 256 + t;
        if (w < 352) { oh[w] = s4h[w]; ol[w] = s4l[w]; }
    }
}

// ========== pack W^T (N rows, KP cols, K-major) as bf16 hi/lo ==========
__global__ void buildWt_kernel(const float* __restrict__ coef, const float* __restrict__ sb_,
                               const float* __restrict__ sp_, __nv_bfloat16* __restrict__ Wh,
                               __nv_bfloat16* __restrict__ Wl, int in, int out, int KP) {
    int idx = blockIdx.x * blockDim.x + threadIdx.x;
    if (idx >= out * KP) return;
    int n = idx / KP, k = idx - n * KP;
    float v = 0.f;
    if (k < in) {
        v = sb_[k * out + n];
    } else if (k < in * 14) {
        int q = k - in;
        int i = q / 13, g = q - i * 13;
        v = coef[((size_t)i * out + n) * 13 + g] * sp_[i * out + n];
    }
    __nv_bfloat16 hi, lo;
    split_hl(v, hi, lo);
    Wh[idx] = hi;
    Wl[idx] = lo;
}

// ========== pack layer-3 W (K rows, 10 cols) as fp32 ==========
__global__ void buildW3_kernel(const float* __restrict__ coef, const float* __restrict__ sb_,
                               const float* __restrict__ sp_, float* __restrict__ W) {
    int idx = blockIdx.x * blockDim.x + threadIdx.x;
    if (idx >= K2 * OUT3) return;
    int r = idx / OUT3, o = idx - r * OUT3;
    float v;
    if (r < HID) {
        v = sb_[r * OUT3 + o];
    } else {
        int q = r - HID;
        int i = q / 13, g = q - i * 13;
        v = coef[((size_t)i * OUT3 + o) * 13 + g] * sp_[i * OUT3 + o];
    }
    W[idx] = v;
}

// ================= HMMA GEMM: C(M,Nc) = (Ah+Al)(M,K) @ (Wh+Wl)^T + bias =================
// 64x128 tile, K-chunk 32 bf16, 3-stage cp.async, 2 CTAs/SM, mma.sync m16n8k16, 3-term split.
#define ASTRIDE     80                 // 64B data + 16B pad: conflict-free ldmatrix
#define AMAT_BYTES  (64 * ASTRIDE)     // 5120
#define BMAT_BYTES  (128 * ASTRIDE)    // 10240
#define STAGE_BYTES (2 * AMAT_BYTES + 2 * BMAT_BYTES)   // 30720
#define SMEM_GEMM   (3 * STAGE_BYTES + 512)

__global__ __launch_bounds__(256, 2)
void gemm_kernel(const __nv_bfloat16* __restrict__ Ah, const __nv_bfloat16* __restrict__ Al,
                 const __nv_bfloat16* __restrict__ Wh, const __nv_bfloat16* __restrict__ Wl,
                 const float* __restrict__ bias, float* __restrict__ C, int K, int Nc) {
    extern __shared__ char smem[];
    uint32_t sbase = smem_to_u32(smem);
    float* bsm = (float*)(smem + 3 * STAGE_BYTES);
    int tid = threadIdx.x, lane = tid & 31, wid = tid >> 5;
    int bm = blockIdx.y * 64, bn = blockIdx.x * 128;
    if (tid < 128) bsm[tid] = bias[bn + tid];

    const size_t strideA = (size_t)K * 2;   // bytes per row
    const char* pAh = (const char*)Ah;
    const char* pAl = (const char*)Al;
    const char* pWh = (const char*)Wh;
    const char* pWl = (const char*)Wl;

    float acc[2][4][4];
#pragma unroll
    for (int i = 0; i < 2; i++)
#pragma unroll
        for (int j = 0; j < 4; j++)
#pragma unroll
            for (int q = 0; q < 4; q++) acc[i][j][q] = 0.f;

    // warp tile: 32 (M) x 32 (N)
    int wm = (wid & 1) * 32, wn = (wid >> 1) * 32;
    int a_row = lane & 15, a_hi = lane >> 4;
    int bg = lane >> 3;
    int b_row = ((bg >> 1) << 3) + (lane & 7);
    int b_hi = bg & 1;

    int nch = K >> 5;

    // per-thread loader assignments (1 cp per A matrix, 2 per B matrix)
    int rowA = tid >> 2, chA = tid & 3;
    uint32_t soffA = rowA * ASTRIDE + chA * 16;

#define LOAD_CHUNK(stage, c) do { \
        size_t kb = (size_t)(c) * 64; \
        uint32_t sst = sbase + (stage) * STAGE_BYTES; \
        size_t ga = (size_t)(bm + rowA) * strideA + kb + chA * 16; \
        CP16(sst + soffA,              pAh + ga); \
        CP16(sst + AMAT_BYTES + soffA, pAl + ga); \
        _Pragma("unroll") \
        for (int u = 0; u < 2; u++) { \
            int idx = u * 256 + tid; \
            int row = idx >> 2, ch = idx & 3; \
            uint32_t soff = row * ASTRIDE + ch * 16; \
            size_t gb = (size_t)(bn + row) * strideA + kb + ch * 16; \
            CP16(sst + 2 * AMAT_BYTES + soff,              pWh + gb); \
            CP16(sst + 2 * AMAT_BYTES + BMAT_BYTES + soff, pWl + gb); \
        } \
    } while (0)

    LOAD_CHUNK(0, 0);
    CP_COMMIT();
    if (nch > 1) { LOAD_CHUNK(1, 1); CP_COMMIT(); }

    int st = 0;
    for (int c = 0; c < nch; c++) {
        if (c + 2 < nch) {
            int s2 = st + 2; if (s2 >= 3) s2 -= 3;
            LOAD_CHUNK(s2, c + 2);
            CP_COMMIT();
            CP_WAIT2();
        } else if (c + 1 < nch) {
            CP_WAIT1();
        } else {
            CP_WAIT0();
        }
        __syncthreads();

        uint32_t base = sbase + st * STAGE_BYTES;
        uint32_t aAh = base, aAl = base + AMAT_BYTES;
        uint32_t aBh = base + 2 * AMAT_BYTES, aBl = aBh + BMAT_BYTES;

#pragma unroll
        for (int kk = 0; kk < 2; kk++) {
            int kch = kk * 2;
            uint32_t ahf[2][4], alf[2][4], bhf[2][4], blf[2][4];
#pragma unroll
            for (int mt = 0; mt < 2; mt++) {
                uint32_t ao = (uint32_t)(wm + mt * 16 + a_row) * ASTRIDE + (kch + a_hi) * 16;
                LDSM4(ahf[mt], aAh + ao);
                LDSM4(alf[mt], aAl + ao);
            }
#pragma unroll
            for (int np = 0; np < 2; np++) {
                uint32_t bo = (uint32_t)(wn + np * 16 + b_row) * ASTRIDE + (kch + b_hi) * 16;
                LDSM4(bhf[np], aBh + bo);
                LDSM4(blf[np], aBl + bo);
            }
#pragma unroll
            for (int mt = 0; mt < 2; mt++)
#pragma unroll
                for (int nt = 0; nt < 4; nt++) {
                    int np = nt >> 1, s = (nt & 1) * 2;
                    MMA_BF16(acc[mt][nt], ahf[mt], bhf[np][s], bhf[np][s + 1]);
                    MMA_BF16(acc[mt][nt], ahf[mt], blf[np][s], blf[np][s + 1]);
                    MMA_BF16(acc[mt][nt], alf[mt], bhf[np][s], bhf[np][s + 1]);
                }
        }
        __syncthreads();
        if (++st == 3) st = 0;
    }
#undef LOAD_CHUNK

#pragma unroll
    for (int mt = 0; mt < 2; mt++) {
        int r0 = bm + wm + mt * 16 + (lane >> 2);
#pragma unroll
        for (int nt = 0; nt < 4; nt++) {
            int cl = wn + nt * 8 + (lane & 3) * 2;
            float bz0 = bsm[cl], bz1 = bsm[cl + 1];
            float2 v0, v1;
            v0.x = acc[mt][nt][0] + bz0;  v0.y = acc[mt][nt][1] + bz1;
            v1.x = acc[mt][nt][2] + bz0;  v1.y = acc[mt][nt][3] + bz1;
            *(float2*)(C + (size_t)r0 * Nc + bn + cl)       = v0;
            *(float2*)(C + (size_t)(r0 + 8) * Nc + bn + cl) = v1;
        }
    }
}

// ================= layer3: (B,3584)@(3584,10) + bias, fused log_softmax, split-K =================
__global__ __launch_bounds__(256)
void layer3_kernel(const __nv_bfloat16* __restrict__ Ah, const __nv_bfloat16* __restrict__ Al,
                   const float* __restrict__ W3, const float* __restrict__ bias,
                   float* __restrict__ out) {
    __shared__ float At[2][128][33];
    __shared__ float Ws[2][320];
    __shared__ float red[128][10];
    int t = threadIdx.x;
    int h = t >> 7, tr = t & 127;
    int r0 = blockIdx.x * 128;
    float acc[10];
#pragma unroll
    for (int o = 0; o < 10; o++) acc[o] = 0.f;

    int kbeg = h * 1792;
    for (int ki = 0; ki < 1792; ki += 32) {
        int k0 = kbeg + ki;
#pragma unroll
        for (int u = 0; u < 4; u++) {
            int idx = u * 128 + tr;
            int row = idx >> 2, q = idx & 3;
            size_t gb = ((size_t)(r0 + row) * K2 + k0) * 2 + q * 16;
            uint4 vh = *(const uint4*)((const char*)Ah + gb);
            uint4 vl = *(const uint4*)((const char*)Al + gb);
            const __nv_bfloat162* hh = (const __nv_bfloat162*)&vh;
            const __nv_bfloat162* ll = (const __nv_bfloat162*)&vl;
            float* dst = &At[h][row][q * 8];
#pragma unroll
            for (int j = 0; j < 4; j++) {
                float2 a = __bfloat1622float2(hh[j]);
                float2 b = __bfloat1622float2(ll[j]);
                dst[j * 2 + 0] = a.x + b.x;
                dst[j * 2 + 1] = a.y + b.y;
            }
        }
        for (int w = tr; w < 320; w += 128)
            Ws[h][w] = W3[(size_t)(k0 + w / 10) * 10 + (w % 10)];
        __syncthreads();
#pragma unroll
        for (int kk = 0; kk < 32; kk++) {
            float a = At[h][tr][kk];
#pragma unroll
            for (int o = 0; o < 10; o++) acc[o] = fmaf(a, Ws[h][kk * 10 + o], acc[o]);
        }
        __syncthreads();
    }
    if (h == 1) {
#pragma unroll
        for (int o = 0; o < 10; o++) red[tr][o] = acc[o];
    }
    __syncthreads();
    if (h == 0) {
#pragma unroll
        for (int o = 0; o < 10; o++) acc[o] += red[tr][o] + bias[o];
        float m = acc[0];
#pragma unroll
        for (int o = 1; o < 10; o++) m = fmaxf(m, acc[o]);
        float s = 0.f;
#pragma unroll
        for (int o = 0; o < 10; o++) s += expf(acc[o] - m);
        float ls = logf(s) + m;
        int row = r0 + tr;
#pragma unroll
        for (int o = 0; o < 10; o++) out[(size_t)row * 10 + o] = acc[o] - ls;
    }
}

// ================= host =================
extern "C" void kernel_launch(void* const* d_in, const int* in_sizes, int n_in,
                              void* d_out, int out_size) {
    const float* x     = (const float*)d_in[0];
    const float* coef1 = (const float*)d_in[1];
    const float* sb1   = (const float*)d_in[2];
    const float* sp1   = (const float*)d_in[3];
    const float* b1    = (const float*)d_in[4];
    const float* coef2 = (const float*)d_in[5];
    const float* sb2   = (const float*)d_in[6];
    const float* sp2   = (const float*)d_in[7];
    const float* b2    = (const float*)d_in[8];
    const float* coef3 = (const float*)d_in[9];
    const float* sb3   = (const float*)d_in[10];
    const float* sp3   = (const float*)d_in[11];
    const float* b3    = (const float*)d_in[12];
    float* out = (float*)d_out;

    float *H, *W3;
    __nv_bfloat16 *Ah, *Al, *Wh1, *Wl1, *Wh2, *Wl2;
    cudaGetSymbolAddress((void**)&H,   g_H);
    cudaGetSymbolAddress((void**)&Ah,  g_Ah);
    cudaGetSymbolAddress((void**)&Al,  g_Al);
    cudaGetSymbolAddress((void**)&Wh1, g_Wh1);
    cudaGetSymbolAddress((void**)&Wl1, g_Wl1);
    cudaGetSymbolAddress((void**)&Wh2, g_Wh2);
    cudaGetSymbolAddress((void**)&Wl2, g_Wl2);
    cudaGetSymbolAddress((void**)&W3,  g_W3);

    cudaFuncSetAttribute(gemm_kernel, cudaFuncAttributeMaxDynamicSharedMemorySize, SMEM_GEMM);

    dim3 g1(HID / 128, BATCH / 64);   // (2, 128) = 256 CTAs

    buildWt_kernel<<<(HID * KP1 + 255) / 256, 256>>>(coef1, sb1, sp1, Wh1, Wl1, IN1, HID, KP1); // 0
    buildWt_kernel<<<(HID * K2 + 255) / 256, 256>>>(coef2, sb2, sp2, Wh2, Wl2, HID, HID, K2);   // 1
    expand49_kernel<<<BATCH / 4, 256>>>(x, Ah, Al);                                              // 2
    gemm_kernel<<<g1, 256, SMEM_GEMM>>>(Ah, Al, Wh1, Wl1, b1, H, KP1, HID);                      // 3 (ncu)
    expand256_kernel<<<BATCH, 256>>>(H, Ah, Al);                                                 // 4
    gemm_kernel<<<g1, 256, SMEM_GEMM>>>(Ah, Al, Wh2, Wl2, b2, H, K2, HID);                       // 5
    expand256_kernel<<<BATCH, 256>>>(H, Ah, Al);                                                 // 6
    buildW3_kernel<<<(K2 * OUT3 + 255) / 256, 256>>>(coef3, sb3, sp3, W3);                       // 7
    layer3_kernel<<<BATCH / 128, 256>>>(Ah, Al, W3, b3, out);                                    // 8
}

// round 9
// speedup vs baseline: 1.4301x; 1.4301x over previous
#include <cuda_runtime.h>
#include <cuda_bf16.h>
#include <cstdint>
#include <math.h>

#define BATCH 8192
#define IN1   49
#define HID   256
#define NCOEF 13
#define KP1   704      // 49*14 = 686, padded to 64-multiple
#define K2    3584     // 256*14
#define OUT3  10

// ================= helpers (baseline PTX only: sm_80-era features) =================
__device__ __forceinline__ uint32_t smem_to_u32(const void* p) {
    uint32_t a;
    asm("{ .reg .u64 t; cvta.to.shared.u64 t, %1; cvt.u32.u64 %0, t; }" : "=r"(a) : "l"(p));
    return a;
}

#define CP16(dst, src) \
    asm volatile("cp.async.cg.shared.global [%0], [%1], 16;" :: "r"(dst), "l"(src) : "memory")
#define CP_COMMIT() asm volatile("cp.async.commit_group;" ::: "memory")
#define CP_WAIT2()  asm volatile("cp.async.wait_group 2;" ::: "memory")
#define CP_WAIT1()  asm volatile("cp.async.wait_group 1;" ::: "memory")
#define CP_WAIT0()  asm volatile("cp.async.wait_group 0;" ::: "memory")

#define LDSM4(r, addr) \
    asm volatile("ldmatrix.sync.aligned.m8n8.x4.shared.b16 {%0,%1,%2,%3}, [%4];" \
        : "=r"((r)[0]), "=r"((r)[1]), "=r"((r)[2]), "=r"((r)[3]) : "r"(addr))

#define MMA_BF16(d, a, b0, b1) \
    asm volatile("mma.sync.aligned.m16n8k16.row.col.f32.bf16.bf16.f32 " \
        "{%0,%1,%2,%3},{%4,%5,%6,%7},{%8,%9},{%0,%1,%2,%3};" \
        : "+f"((d)[0]), "+f"((d)[1]), "+f"((d)[2]), "+f"((d)[3]) \
        : "r"((a)[0]), "r"((a)[1]), "r"((a)[2]), "r"((a)[3]), "r"(b0), "r"(b1))

// ================= scratch =================
__device__ float         g_H [BATCH * HID];
__device__ __nv_bfloat16 g_Ah[(size_t)BATCH * K2];
__device__ __nv_bfloat16 g_Al[(size_t)BATCH * K2];
__device__ __nv_bfloat16 g_Wh1[HID * KP1];
__device__ __nv_bfloat16 g_Wl1[HID * KP1];
__device__ __nv_bfloat16 g_Wh2[HID * K2];
__device__ __nv_bfloat16 g_Wl2[HID * K2];
__device__ float         g_W3[K2 * OUT3];

// ================= shared KAN basis math =================
__device__ __forceinline__ void kan_basis(float xv, float& mishv, float* Bv) {
    float sp = fmaxf(xv, 0.f) + log1pf(expf(-fabsf(xv)));
    mishv = xv * tanhf(sp);
    const float h = 0.4f;
#pragma unroll
    for (int j = 0; j < 16; j++) {
        float t0 = -2.0f + h * (float)(j - 3);
        float t1 = -2.0f + h * (float)(j - 2);
        Bv[j] = (xv >= t0 && xv < t1) ? 1.0f : 0.0f;
    }
#pragma unroll
    for (int d = 1; d <= 3; d++) {
        float inv = 1.0f / (h * (float)d);
#pragma unroll
        for (int j = 0; j < 16 - 3; j++) {
            if (j < 16 - d) {
                float tj   = -2.0f + h * (float)(j - 3);
                float tjd1 = -2.0f + h * (float)(j - 3 + d + 1);
                Bv[j] = (xv - tj) * inv * Bv[j] + (tjd1 - xv) * inv * Bv[j + 1];
            }
        }
        if (d < 3) {
            for (int j = 13; j < 16 - d; j++) {
                float tj   = -2.0f + h * (float)(j - 3);
                float tjd1 = -2.0f + h * (float)(j - 3 + d + 1);
                Bv[j] = (xv - tj) * inv * Bv[j] + (tjd1 - xv) * inv * Bv[j + 1];
            }
        }
    }
}

__device__ __forceinline__ void split_hl(float v, __nv_bfloat16& hi, __nv_bfloat16& lo) {
    hi = __float2bfloat16(v);
    lo = __float2bfloat16(v - __bfloat162float(hi));
}

// ========== expand for in=256 (layer 2 input): 1 batch row per block, smem-staged ==========
__global__ __launch_bounds__(256)
void expand256_kernel(const float* __restrict__ H, __nv_bfloat16* __restrict__ Ah,
                      __nv_bfloat16* __restrict__ Al) {
    __shared__ __nv_bfloat16 sh[K2];
    __shared__ __nv_bfloat16 sl[K2];
    int b = blockIdx.x, i = threadIdx.x;
    float xv = H[b * HID + i];
    float mishv, Bv[16];
    kan_basis(xv, mishv, Bv);
    split_hl(mishv, sh[i], sl[i]);
    int off = HID + i * NCOEF;
#pragma unroll
    for (int g = 0; g < NCOEF; g++) split_hl(Bv[g], sh[off + g], sl[off + g]);
    __syncthreads();

    const uint4* s4h = (const uint4*)sh;
    const uint4* s4l = (const uint4*)sl;
    uint4* oh = (uint4*)(Ah + (size_t)b * K2);
    uint4* ol = (uint4*)(Al + (size_t)b * K2);
#pragma unroll
    for (int u = 0; u < 2; u++) {
        int t = u * 256 + i;
        if (t < 448) { oh[t] = s4h[t]; ol[t] = s4l[t]; }
    }
}

// ========== expand for layer 1: fused pool + basis + pad; 4 batch rows per block ==========
__global__ __launch_bounds__(256)
void expand49_kernel(const float* __restrict__ x, __nv_bfloat16* __restrict__ Ah,
                     __nv_bfloat16* __restrict__ Al) {
    __shared__ __nv_bfloat16 sh[4 * KP1];
    __shared__ __nv_bfloat16 sl[4 * KP1];
    int t = threadIdx.x;
    int b0 = blockIdx.x * 4;
    __nv_bfloat16 z = __float2bfloat16(0.f);

    if (t < 72) {
        int r = t / 18, c = 686 + (t - (t / 18) * 18);
        sh[r * KP1 + c] = z;
        sl[r * KP1 + c] = z;
    }

    if (t < 196) {
        int r = t / 49, i = t - r * 49;
        int b = b0 + r;
        int pr = i / 7, pc = i - pr * 7;
        const float* base = x + (size_t)b * 784 + pr * 4 * 28 + pc * 4;
        float s = 0.f;
#pragma unroll
        for (int k = 0; k < 4; k++) {
            float4 v = *(const float4*)(base + k * 28);
            s += v.x + v.y + v.z + v.w;
        }
        float xv = s * 0.0625f;
        float mishv, Bv[16];
        kan_basis(xv, mishv, Bv);
        __nv_bfloat16* rh = sh + r * KP1;
        __nv_bfloat16* rl = sl + r * KP1;
        split_hl(mishv, rh[i], rl[i]);
        int off = IN1 + i * NCOEF;
#pragma unroll
        for (int g = 0; g < NCOEF; g++) split_hl(Bv[g], rh[off + g], rl[off + g]);
    }
    __syncthreads();

    const uint4* s4h = (const uint4*)sh;
    const uint4* s4l = (const uint4*)sl;
    uint4* oh = (uint4*)(Ah + (size_t)b0 * KP1);
    uint4* ol = (uint4*)(Al + (size_t)b0 * KP1);
#pragma unroll
    for (int u = 0; u < 2; u++) {
        int w = u * 256 + t;
        if (w < 352) { oh[w] = s4h[w]; ol[w] = s4l[w]; }
    }
}

// ========== pack W^T (N rows, KP cols, K-major) as bf16 hi/lo ==========
__global__ void buildWt_kernel(const float* __restrict__ coef, const float* __restrict__ sb_,
                               const float* __restrict__ sp_, __nv_bfloat16* __restrict__ Wh,
                               __nv_bfloat16* __restrict__ Wl, int in, int out, int KP) {
    int idx = blockIdx.x * blockDim.x + threadIdx.x;
    if (idx >= out * KP) return;
    int n = idx / KP, k = idx - n * KP;
    float v = 0.f;
    if (k < in) {
        v = sb_[k * out + n];
    } else if (k < in * 14) {
        int q = k - in;
        int i = q / 13, g = q - i * 13;
        v = coef[((size_t)i * out + n) * 13 + g] * sp_[i * out + n];
    }
    __nv_bfloat16 hi, lo;
    split_hl(v, hi, lo);
    Wh[idx] = hi;
    Wl[idx] = lo;
}

// ========== pack layer-3 W (K rows, 10 cols) as fp32 ==========
__global__ void buildW3_kernel(const float* __restrict__ coef, const float* __restrict__ sb_,
                               const float* __restrict__ sp_, float* __restrict__ W) {
    int idx = blockIdx.x * blockDim.x + threadIdx.x;
    if (idx >= K2 * OUT3) return;
    int r = idx / OUT3, o = idx - r * OUT3;
    float v;
    if (r < HID) {
        v = sb_[r * OUT3 + o];
    } else {
        int q = r - HID;
        int i = q / 13, g = q - i * 13;
        v = coef[((size_t)i * OUT3 + o) * 13 + g] * sp_[i * OUT3 + o];
    }
    W[idx] = v;
}

// ================= HMMA GEMM: C(M,Nc) = (Ah+Al)(M,K) @ (Wh+Wl)^T + bias =================
// 64x128 tile, K-chunk 32 bf16, 3-stage cp.async, mma.sync m16n8k16, 3-term split.
#define ASTRIDE     80                 // 64B data + 16B pad: conflict-free ldmatrix
#define AMAT_BYTES  (64 * ASTRIDE)     // 5120
#define BMAT_BYTES  (128 * ASTRIDE)    // 10240
#define STAGE_BYTES (2 * AMAT_BYTES + 2 * BMAT_BYTES)   // 30720
#define SMEM_GEMM   (3 * STAGE_BYTES + 512)

__global__ __launch_bounds__(256, 2)
void gemm_kernel(const __nv_bfloat16* __restrict__ Ah, const __nv_bfloat16* __restrict__ Al,
                 const __nv_bfloat16* __restrict__ Wh, const __nv_bfloat16* __restrict__ Wl,
                 const float* __restrict__ bias, float* __restrict__ C, int K, int Nc) {
    extern __shared__ char smem[];
    uint32_t sbase = smem_to_u32(smem);
    float* bsm = (float*)(smem + 3 * STAGE_BYTES);
    int tid = threadIdx.x, lane = tid & 31, wid = tid >> 5;
    int bm = blockIdx.y * 64, bn = blockIdx.x * 128;
    if (tid < 128) bsm[tid] = bias[bn + tid];

    const size_t strideA = (size_t)K * 2;   // bytes per row
    const char* pAh = (const char*)Ah;
    const char* pAl = (const char*)Al;
    const char* pWh = (const char*)Wh;
    const char* pWl = (const char*)Wl;

    float acc[2][4][4];
#pragma unroll
    for (int i = 0; i < 2; i++)
#pragma unroll
        for (int j = 0; j < 4; j++)
#pragma unroll
            for (int q = 0; q < 4; q++) acc[i][j][q] = 0.f;

    // warp tile: 32 (M) x 32 (N)
    int wm = (wid & 1) * 32, wn = (wid >> 1) * 32;
    int a_row = lane & 15, a_hi = lane >> 4;
    int bg = lane >> 3;
    int b_row = ((bg >> 1) << 3) + (lane & 7);
    int b_hi = bg & 1;

    int nch = K >> 5;

    int rowA = tid >> 2, chA = tid & 3;
    uint32_t soffA = rowA * ASTRIDE + chA * 16;

#define LOAD_CHUNK(stage, c) do { \
        size_t kb = (size_t)(c) * 64; \
        uint32_t sst = sbase + (stage) * STAGE_BYTES; \
        size_t ga = (size_t)(bm + rowA) * strideA + kb + chA * 16; \
        CP16(sst + soffA,              pAh + ga); \
        CP16(sst + AMAT_BYTES + soffA, pAl + ga); \
        _Pragma("unroll") \
        for (int u = 0; u < 2; u++) { \
            int idx = u * 256 + tid; \
            int row = idx >> 2, ch = idx & 3; \
            uint32_t soff = row * ASTRIDE + ch * 16; \
            size_t gb = (size_t)(bn + row) * strideA + kb + ch * 16; \
            CP16(sst + 2 * AMAT_BYTES + soff,              pWh + gb); \
            CP16(sst + 2 * AMAT_BYTES + BMAT_BYTES + soff, pWl + gb); \
        } \
    } while (0)

    LOAD_CHUNK(0, 0);
    CP_COMMIT();
    if (nch > 1) { LOAD_CHUNK(1, 1); CP_COMMIT(); }

    int st = 0;
    for (int c = 0; c < nch; c++) {
        if (c + 2 < nch) {
            int s2 = st + 2; if (s2 >= 3) s2 -= 3;
            LOAD_CHUNK(s2, c + 2);
            CP_COMMIT();
            CP_WAIT2();
        } else if (c + 1 < nch) {
            CP_WAIT1();
        } else {
            CP_WAIT0();
        }
        __syncthreads();

        uint32_t base = sbase + st * STAGE_BYTES;
        uint32_t aAh = base, aAl = base + AMAT_BYTES;
        uint32_t aBh = base + 2 * AMAT_BYTES, aBl = aBh + BMAT_BYTES;

#pragma unroll
        for (int kk = 0; kk < 2; kk++) {
            int kch = kk * 2;
            uint32_t ahf[2][4], alf[2][4], bhf[2][4], blf[2][4];
#pragma unroll
            for (int mt = 0; mt < 2; mt++) {
                uint32_t ao = (uint32_t)(wm + mt * 16 + a_row) * ASTRIDE + (kch + a_hi) * 16;
                LDSM4(ahf[mt], aAh + ao);
                LDSM4(alf[mt], aAl + ao);
            }
#pragma unroll
            for (int np = 0; np < 2; np++) {
                uint32_t bo = (uint32_t)(wn + np * 16 + b_row) * ASTRIDE + (kch + b_hi) * 16;
                LDSM4(bhf[np], aBh + bo);
                LDSM4(blf[np], aBl + bo);
            }
#pragma unroll
            for (int mt = 0; mt < 2; mt++)
#pragma unroll
                for (int nt = 0; nt < 4; nt++) {
                    int np = nt >> 1, s = (nt & 1) * 2;
                    MMA_BF16(acc[mt][nt], ahf[mt], bhf[np][s], bhf[np][s + 1]);
                    MMA_BF16(acc[mt][nt], ahf[mt], blf[np][s], blf[np][s + 1]);
                    MMA_BF16(acc[mt][nt], alf[mt], bhf[np][s], bhf[np][s + 1]);
                }
        }
        __syncthreads();
        if (++st == 3) st = 0;
    }
#undef LOAD_CHUNK

#pragma unroll
    for (int mt = 0; mt < 2; mt++) {
        int r0 = bm + wm + mt * 16 + (lane >> 2);
#pragma unroll
        for (int nt = 0; nt < 4; nt++) {
            int cl = wn + nt * 8 + (lane & 3) * 2;
            float bz0 = bsm[cl], bz1 = bsm[cl + 1];
            float2 v0, v1;
            v0.x = acc[mt][nt][0] + bz0;  v0.y = acc[mt][nt][1] + bz1;
            v1.x = acc[mt][nt][2] + bz0;  v1.y = acc[mt][nt][3] + bz1;
            *(float2*)(C + (size_t)r0 * Nc + bn + cl)       = v0;
            *(float2*)(C + (size_t)(r0 + 8) * Nc + bn + cl) = v1;
        }
    }
}

// ===== layer3 fused: H(B,256) -> expand inline -> @W3(3584,10) + bias -> log_softmax =====
// 64 rows per block, 256 threads (4 threads per row), chunks of 32 inputs.
#define L3_ROWS 64
__global__ __launch_bounds__(256)
void layer3_fused_kernel(const float* __restrict__ H, const float* __restrict__ W3,
                         const float* __restrict__ bias, float* __restrict__ out) {
    __shared__ float Hs[L3_ROWS * 33];      // stride 33: conflict-free
    __shared__ float Wm[32 * 10];           // mish weights for this i-chunk
    __shared__ float Wsp[32 * 13 * 10];     // spline weights for this i-chunk
    __shared__ float bs[10];
    int t = threadIdx.x;
    int r0 = blockIdx.x * L3_ROWS;
    int rl = t >> 2, sub = t & 3;
    if (t < 10) bs[t] = bias[t];

    float acc[10];
#pragma unroll
    for (int o = 0; o < 10; o++) acc[o] = 0.f;

    for (int i0 = 0; i0 < HID; i0 += 32) {
        __syncthreads();
        // H slice: rows [r0, r0+64), cols [i0, i0+32)
        for (int idx = t; idx < L3_ROWS * 32; idx += 256) {
            int row = idx >> 5, col = idx & 31;
            Hs[row * 33 + col] = H[(size_t)(r0 + row) * HID + i0 + col];
        }
        // mish weights: W3 rows [i0, i0+32)
        for (int idx = t; idx < 320; idx += 256)
            Wm[idx] = W3[(size_t)i0 * 10 + idx];
        // spline weights: W3 rows [256 + i0*13, 256 + (i0+32)*13) -> 4160 contiguous floats
        for (int idx = t; idx < 4160; idx += 256)
            Wsp[idx] = W3[(size_t)(HID + i0 * 13) * 10 + idx];
        __syncthreads();

        for (int ii = sub; ii < 32; ii += 4) {
            float xv = Hs[rl * 33 + ii];
            float mishv, Bv[16];
            kan_basis(xv, mishv, Bv);
            const float* wm  = &Wm[ii * 10];
            const float* wsp = &Wsp[ii * 130];
#pragma unroll
            for (int o = 0; o < 10; o++) acc[o] = fmaf(mishv, wm[o], acc[o]);
#pragma unroll
            for (int g = 0; g < NCOEF; g++) {
                float bg = Bv[g];
#pragma unroll
                for (int o = 0; o < 10; o++) acc[o] = fmaf(bg, wsp[g * 10 + o], acc[o]);
            }
        }
    }

    // reduce across the 4 threads of each row (consecutive lanes)
#pragma unroll
    for (int o = 0; o < 10; o++) {
        acc[o] += __shfl_xor_sync(0xFFFFFFFF, acc[o], 1);
        acc[o] += __shfl_xor_sync(0xFFFFFFFF, acc[o], 2);
    }
    if (sub == 0) {
#pragma unroll
        for (int o = 0; o < 10; o++) acc[o] += bs[o];
        float m = acc[0];
#pragma unroll
        for (int o = 1; o < 10; o++) m = fmaxf(m, acc[o]);
        float s = 0.f;
#pragma unroll
        for (int o = 0; o < 10; o++) s += expf(acc[o] - m);
        float ls = logf(s) + m;
        int row = r0 + rl;
#pragma unroll
        for (int o = 0; o < 10; o++) out[(size_t)row * 10 + o] = acc[o] - ls;
    }
}

// ================= host =================
extern "C" void kernel_launch(void* const* d_in, const int* in_sizes, int n_in,
                              void* d_out, int out_size) {
    const float* x     = (const float*)d_in[0];
    const float* coef1 = (const float*)d_in[1];
    const float* sb1   = (const float*)d_in[2];
    const float* sp1   = (const float*)d_in[3];
    const float* b1    = (const float*)d_in[4];
    const float* coef2 = (const float*)d_in[5];
    const float* sb2   = (const float*)d_in[6];
    const float* sp2   = (const float*)d_in[7];
    const float* b2    = (const float*)d_in[8];
    const float* coef3 = (const float*)d_in[9];
    const float* sb3   = (const float*)d_in[10];
    const float* sp3   = (const float*)d_in[11];
    const float* b3    = (const float*)d_in[12];
    float* out = (float*)d_out;

    float *H, *W3;
    __nv_bfloat16 *Ah, *Al, *Wh1, *Wl1, *Wh2, *Wl2;
    cudaGetSymbolAddress((void**)&H,   g_H);
    cudaGetSymbolAddress((void**)&Ah,  g_Ah);
    cudaGetSymbolAddress((void**)&Al,  g_Al);
    cudaGetSymbolAddress((void**)&Wh1, g_Wh1);
    cudaGetSymbolAddress((void**)&Wl1, g_Wl1);
    cudaGetSymbolAddress((void**)&Wh2, g_Wh2);
    cudaGetSymbolAddress((void**)&Wl2, g_Wl2);
    cudaGetSymbolAddress((void**)&W3,  g_W3);

    cudaFuncSetAttribute(gemm_kernel, cudaFuncAttributeMaxDynamicSharedMemorySize, SMEM_GEMM);

    dim3 g1(HID / 128, BATCH / 64);   // (2, 128) = 256 CTAs

    buildWt_kernel<<<(HID * KP1 + 255) / 256, 256>>>(coef1, sb1, sp1, Wh1, Wl1, IN1, HID, KP1); // 0
    buildWt_kernel<<<(HID * K2 + 255) / 256, 256>>>(coef2, sb2, sp2, Wh2, Wl2, HID, HID, K2);   // 1
    expand49_kernel<<<BATCH / 4, 256>>>(x, Ah, Al);                                              // 2
    gemm_kernel<<<g1, 256, SMEM_GEMM>>>(Ah, Al, Wh1, Wl1, b1, H, KP1, HID);                      // 3 (ncu)
    expand256_kernel<<<BATCH, 256>>>(H, Ah, Al);                                                 // 4
    gemm_kernel<<<g1, 256, SMEM_GEMM>>>(Ah, Al, Wh2, Wl2, b2, H, K2, HID);                       // 5
    buildW3_kernel<<<(K2 * OUT3 + 255) / 256, 256>>>(coef3, sb3, sp3, W3);                       // 6
    layer3_fused_kernel<<<BATCH / L3_ROWS, 256>>>(H, W3, b3, out);                               // 7
}